// round 12
// baseline (speedup 1.0000x reference)
#include <cuda_runtime.h>
#include <math.h>

static constexpr int NN = 100000;   // nodes (capacity)
static constexpr int EE = 1600000;  // edges (capacity)
static constexpr int DD = 64;
static constexpr int SCAN_B = 1024;
static constexpr int NB_MAX = (NN + SCAN_B - 1) / SCAN_B;   // <= 98 for N=100K

// Scratch (static device globals; no allocation anywhere).
// Invariants self-restore per launch: cnt re-zeroed by k_scanfused, sf/st
// re-zeroed by k_seg, barrier reset by k_histnode -> graph replays OK.
__device__ __align__(16) float  g_z[(size_t)NN * DD];  // 25.6 MB z result
__device__ float  g_as[NN], g_ad[NN];                  // per-node logit halves
__device__ float  g_norm[NN];                          // ||tax_n||
__device__ int    g_Mi;                                // max norm (float bits; pos -> int cmp ok)
__device__ int    g_cnt[NN];                           // in-degree histogram (zero at launch start)
__device__ int    g_off[NN];                           // CSR row start
__device__ int    g_pos[NN];                           // scatter cursor -> row end
__device__ float  g_sf[NN], g_st[NN];                  // softmax denominators (zero at launch start)
__device__ __align__(8) float2 g_e2[EE];               // (e_f, e_t) in CSR order
__device__ int    g_src2[EE];                          // src in CSR order
__device__ int    g_bsum[NB_MAX];                      // block sums for scan
__device__ int    g_barrier;                           // grid barrier counter

// ---------------------------------------------------------------------------
// K1: fused dst-histogram + per-node dots a_s, a_d + ||tax|| + global max norm
__global__ void k_histnode(const float* __restrict__ h, const float* __restrict__ tax,
                           const float* __restrict__ wh, const int* __restrict__ dst,
                           int n, int e) {
    int gt = blockIdx.x * blockDim.x + threadIdx.x;
    if (gt == 0) g_barrier = 0;
    if (gt < e) atomicAdd(&g_cnt[dst[gt]], 1);        // cnt==0 invariant at start
    int w = gt >> 5, lane = gt & 31;
    if (w >= n) return;
    float2 hv = *reinterpret_cast<const float2*>(h + (size_t)w * DD + lane * 2);
    float2 tv = *reinterpret_cast<const float2*>(tax + (size_t)w * DD + lane * 2);
    float2 wa = *reinterpret_cast<const float2*>(wh + lane * 2);
    float2 wb = *reinterpret_cast<const float2*>(wh + DD + lane * 2);
    float ps = hv.x * wa.x + hv.y * wa.y;
    float pd = hv.x * wb.x + hv.y * wb.y;
    float nq = tv.x * tv.x + tv.y * tv.y;
#pragma unroll
    for (int o = 16; o; o >>= 1) {
        ps += __shfl_xor_sync(0xffffffffu, ps, o);
        pd += __shfl_xor_sync(0xffffffffu, pd, o);
        nq += __shfl_xor_sync(0xffffffffu, nq, o);
    }
    if (lane == 0) {
        g_as[w] = ps;
        g_ad[w] = pd;
        float nr = sqrtf(nq);
        g_norm[w] = nr;
        atomicMax(&g_Mi, __float_as_int(nr));          // idempotent across replays
    }
}

// K2: fused exclusive scan (98 co-resident blocks, manual grid barrier);
//     re-zeroes g_cnt after consuming it
__global__ void k_scanfused(int n, int nb) {
    __shared__ int sh[SCAN_B];
    __shared__ int bsc[128];
    __shared__ int base;
    int bid = blockIdx.x;
    int i = bid * SCAN_B + threadIdx.x;
    int v = (i < n) ? g_cnt[i] : 0;
    sh[threadIdx.x] = v;
    __syncthreads();
#pragma unroll
    for (int d = 1; d < SCAN_B; d <<= 1) {
        int u = (threadIdx.x >= d) ? sh[threadIdx.x - d] : 0;
        __syncthreads();
        sh[threadIdx.x] += u;
        __syncthreads();
    }
    if (threadIdx.x == SCAN_B - 1) {
        g_bsum[bid] = sh[SCAN_B - 1];
        __threadfence();
        atomicAdd(&g_barrier, 1);
    }
    if (threadIdx.x == 0) {
        while (atomicAdd(&g_barrier, 0) < nb) __nanosleep(64);
    }
    __syncthreads();
    if (threadIdx.x < nb) bsc[threadIdx.x] = g_bsum[threadIdx.x];
    __syncthreads();
    if (threadIdx.x == 0) {
        int s = 0;
        for (int k = 0; k < bid; k++) s += bsc[k];
        base = s;
    }
    __syncthreads();
    if (i < n) {
        int off = base + sh[threadIdx.x] - v;   // exclusive
        g_off[i] = off;
        g_pos[i] = off;
        g_cnt[i] = 0;                            // restore invariant
    }
}

// K3: fused edge pass, all fp32. Per-dst shift S_d = ||tax_d||*M - 80
// (d-only -> cancels in softmax; Cauchy-Schwarz bounds p-S_d in [-~64, 80])
__global__ void k_edge(const float* __restrict__ tax, const int* __restrict__ src,
                       const int* __restrict__ dst, int e) {
    int gt = blockIdx.x * blockDim.x + threadIdx.x;
    int w = gt >> 3, l = gt & 7;
    if (w >= e) return;
    int s = src[w], d = dst[w];
    const float4* ts = reinterpret_cast<const float4*>(tax + (size_t)s * DD);
    const float4* td = reinterpret_cast<const float4*>(tax + (size_t)d * DD);
    float4 a0 = ts[l * 2],     b0 = td[l * 2];
    float4 a1 = ts[l * 2 + 1], b1 = td[l * 2 + 1];
    float p = a0.x * b0.x + a0.y * b0.y + a0.z * b0.z + a0.w * b0.w
            + a1.x * b1.x + a1.y * b1.y + a1.z * b1.z + a1.w * b1.w;
#pragma unroll
    for (int o = 4; o; o >>= 1) p += __shfl_xor_sync(0xffffffffu, p, o);
    if (l == 0) {
        float x = g_as[s] + g_ad[d];
        float wf = x >= 0.f ? x : 0.01f * x;      // leaky_relu(0.01); |wf| small
        float M = __int_as_float(g_Mi);
        float shift = g_norm[d] * M - 80.f;
        float ef = __expf(wf);
        float et = __expf(p - shift);
        atomicAdd(&g_sf[d], ef);
        atomicAdd(&g_st[d], et);
        int pos = atomicAdd(&g_pos[d], 1);
        g_e2[pos] = make_float2(ef, et);
        g_src2[pos] = s;
    }
}

// K4 (PROFILED SLOT): segment aggregation, fixed-trip unrolled broadcast.
// One coalesced (src2, e2) chunk load per 32 edges; inner blocks of 8 with
// uniform guards (no break) so 8-16 h-row loads stay in flight per warp.
__global__ void k_seg(const float* __restrict__ h, int n) {
    int gt = blockIdx.x * blockDim.x + threadIdx.x;
    int w = gt >> 5, lane = gt & 31;
    if (w >= n) return;
    int r0 = g_off[w], r1 = g_pos[w];   // cursor == segment end after scatter
    float sfv = g_sf[w], stv = g_st[w];
    if (lane == 0) { g_sf[w] = 0.f; g_st[w] = 0.f; }   // restore invariant
    float2 acc = make_float2(0.f, 0.f);
    if (r1 > r0) {
        float isf = 0.5f / sfv, ist = 0.5f / stv;
        for (int base = r0; base < r1; base += 32) {
            int m = r1 - base; if (m > 32) m = 32;
            int sj = 0; float aj = 0.f;
            if (lane < m) {
                sj = g_src2[base + lane];
                float2 ej = g_e2[base + lane];
                aj = ej.x * isf + ej.y * ist;     // aj = 0 for padded lanes
            }
#pragma unroll
            for (int k0 = 0; k0 < 32; k0 += 8) {
                if (k0 < m) {                      // uniform guard, no break
                    float2 hx[8];
                    float  av[8];
#pragma unroll
                    for (int i = 0; i < 8; i++) {
                        int s = __shfl_sync(0xffffffffu, sj, k0 + i);
                        av[i] = __shfl_sync(0xffffffffu, aj, k0 + i);
                        // padded entries have s=0, a=0 -> harmless load of row 0
                        hx[i] = *reinterpret_cast<const float2*>(h + (size_t)s * DD + lane * 2);
                    }
#pragma unroll
                    for (int i = 0; i < 8; i++) {
                        acc.x += av[i] * hx[i].x;
                        acc.y += av[i] * hx[i].y;
                    }
                }
            }
        }
    }
    *reinterpret_cast<float2*>(g_z + (size_t)w * DD + lane * 2) = acc;
}

// K5: out = z @ W^T + b   (block = (64,4); W transposed in smem, conflict-free)
__global__ void k_out(const float* __restrict__ Ww, const float* __restrict__ Wb,
                      float* __restrict__ out, int n) {
    __shared__ float Ws[DD * DD];   // Ws[k*64 + c] = Ww[c*64 + k]
    __shared__ float bs[DD];
    int tid = threadIdx.y * 64 + threadIdx.x;
    for (int i = tid; i < DD * DD; i += 256) {
        int c = i >> 6, k = i & 63;
        Ws[k * DD + c] = Ww[i];
    }
    if (tid < DD) bs[tid] = Wb[tid];
    __syncthreads();
    int row = blockIdx.x * 4 + threadIdx.y;
    if (row >= n) return;
    int c = threadIdx.x;
    const float* zr = g_z + (size_t)row * DD;
    float acc = bs[c];
#pragma unroll
    for (int k = 0; k < DD; k += 4) {
        float4 zv = *reinterpret_cast<const float4*>(zr + k);
        acc += zv.x * Ws[(k + 0) * DD + c];
        acc += zv.y * Ws[(k + 1) * DD + c];
        acc += zv.z * Ws[(k + 2) * DD + c];
        acc += zv.w * Ws[(k + 3) * DD + c];
    }
    out[(size_t)row * DD + c] = acc;
}

// ---------------------------------------------------------------------------
extern "C" void kernel_launch(void* const* d_in, const int* in_sizes, int n_in,
                              void* d_out, int out_size) {
    const float* h   = (const float*)d_in[0];
    const float* tax = (const float*)d_in[1];
    const int*   src = (const int*)d_in[2];
    const int*   dst = (const int*)d_in[3];
    const float* wh  = (const float*)d_in[4];
    const float* Ww  = (const float*)d_in[5];
    const float* Wb  = (const float*)d_in[6];
    float* out = (float*)d_out;

    int n = in_sizes[0] / DD;
    int e = in_sizes[2];
    int nb = (n + SCAN_B - 1) / SCAN_B;   // 98 for N=100K (all co-resident)

    k_histnode<<<(int)(((long long)n * 32 + 255) / 256), 256>>>(h, tax, wh, dst, n, e); // 1
    k_scanfused<<<nb, SCAN_B>>>(n, nb);                                                 // 2
    k_edge<<<(int)(((long long)e * 8 + 255) / 256), 256>>>(tax, src, dst, e);           // 3
    k_seg<<<(int)(((long long)n * 32 + 255) / 256), 256>>>(h, n);                       // 4 <- profiled
    k_out<<<(n + 3) / 4, dim3(64, 4)>>>(Ww, Wb, out, n);                                // 5
}

// round 13
// speedup vs baseline: 1.2279x; 1.2279x over previous
#include <cuda_runtime.h>
#include <math.h>

static constexpr int NN = 100000;   // nodes (capacity)
static constexpr int EE = 1600000;  // edges (capacity)
static constexpr int DD = 64;

// Scratch (static device globals; no allocation anywhere).
// Per-launch invariants: k_node zeroes sf/st at start of every launch (BSS zero
// makes the first run correct); k_zeroz zeroes g_z before k_scat accumulates.
__device__ __align__(16) float  g_z[(size_t)NN * DD];  // 25.6 MB z accumulator
__device__ float  g_as[NN], g_ad[NN];                  // per-node logit halves
__device__ float  g_norm[NN];                          // ||tax_n||
__device__ int    g_Mi;                                // max norm (float bits; pos -> int cmp ok)
__device__ float  g_sf[NN], g_st[NN];                  // softmax denominators
__device__ __align__(8) float2 g_e2[EE];               // (e_f, e_t), original edge order

// ---------------------------------------------------------------------------
// K1: zero denominators + per-node dots a_s = h.wh[0:64], a_d = h.wh[64:],
//     ||tax|| and global max norm
__global__ void k_node(const float* __restrict__ h, const float* __restrict__ tax,
                       const float* __restrict__ wh, int n) {
    int gt = blockIdx.x * blockDim.x + threadIdx.x;
    if (gt < n) { g_sf[gt] = 0.f; g_st[gt] = 0.f; }
    int w = gt >> 5, lane = gt & 31;
    if (w >= n) return;
    float2 hv = *reinterpret_cast<const float2*>(h + (size_t)w * DD + lane * 2);
    float2 tv = *reinterpret_cast<const float2*>(tax + (size_t)w * DD + lane * 2);
    float2 wa = *reinterpret_cast<const float2*>(wh + lane * 2);
    float2 wb = *reinterpret_cast<const float2*>(wh + DD + lane * 2);
    float ps = hv.x * wa.x + hv.y * wa.y;
    float pd = hv.x * wb.x + hv.y * wb.y;
    float nq = tv.x * tv.x + tv.y * tv.y;
#pragma unroll
    for (int o = 16; o; o >>= 1) {
        ps += __shfl_xor_sync(0xffffffffu, ps, o);
        pd += __shfl_xor_sync(0xffffffffu, pd, o);
        nq += __shfl_xor_sync(0xffffffffu, nq, o);
    }
    if (lane == 0) {
        g_as[w] = ps;
        g_ad[w] = pd;
        float nr = sqrtf(nq);
        g_norm[w] = nr;
        atomicMax(&g_Mi, __float_as_int(nr));   // idempotent across replays
    }
}

// K2: fused edge pass, all fp32. Per-dst shift S_d = ||tax_d||*M - 80
// (d-only -> cancels in softmax; Cauchy-Schwarz bounds p-S_d in [-~64, 80]).
// Writes (e_f, e_t) at the ORIGINAL edge index (contiguous, no CSR).
__global__ void k_edge(const float* __restrict__ tax, const int* __restrict__ src,
                       const int* __restrict__ dst, int e) {
    int gt = blockIdx.x * blockDim.x + threadIdx.x;
    int w = gt >> 3, l = gt & 7;
    if (w >= e) return;
    int s = src[w], d = dst[w];
    const float4* ts = reinterpret_cast<const float4*>(tax + (size_t)s * DD);
    const float4* td = reinterpret_cast<const float4*>(tax + (size_t)d * DD);
    float4 a0 = ts[l * 2],     b0 = td[l * 2];
    float4 a1 = ts[l * 2 + 1], b1 = td[l * 2 + 1];
    float p = a0.x * b0.x + a0.y * b0.y + a0.z * b0.z + a0.w * b0.w
            + a1.x * b1.x + a1.y * b1.y + a1.z * b1.z + a1.w * b1.w;
#pragma unroll
    for (int o = 4; o; o >>= 1) p += __shfl_xor_sync(0xffffffffu, p, o);
    if (l == 0) {
        float x = g_as[s] + g_ad[d];
        float wf = x >= 0.f ? x : 0.01f * x;      // leaky_relu(0.01); |wf| small
        float M = __int_as_float(g_Mi);
        float shift = g_norm[d] * M - 80.f;
        float ef = __expf(wf);
        float et = __expf(p - shift);
        atomicAdd(&g_sf[d], ef);
        atomicAdd(&g_st[d], et);
        g_e2[w] = make_float2(ef, et);
    }
}

// K3: zero z accumulator (must precede k_scat every launch/replay)
__global__ void k_zeroz(int n) {
    int i = blockIdx.x * blockDim.x + threadIdx.x;
    if (i < n * (DD / 4))
        reinterpret_cast<float4*>(g_z)[i] = make_float4(0.f, 0.f, 0.f, 0.f);
}

// K4 (PROFILED SLOT): edge-parallel scatter. 16 threads/edge, zero serial
// chains: alpha from denominators + h row gather + red.global.add.v4.
__global__ void k_scat(const float* __restrict__ h, const int* __restrict__ src,
                       const int* __restrict__ dst, int e) {
    int gt = blockIdx.x * blockDim.x + threadIdx.x;
    int w = gt >> 4, l = gt & 15;
    if (w >= e) return;
    int s = src[w], d = dst[w];
    float2 ev = g_e2[w];
    float a = ev.x * (0.5f / g_sf[d]) + ev.y * (0.5f / g_st[d]);
    float4 hv = *reinterpret_cast<const float4*>(h + (size_t)s * DD + l * 4);
    float* zp = g_z + (size_t)d * DD + l * 4;
    asm volatile("red.global.add.v4.f32 [%0], {%1, %2, %3, %4};"
                 :: "l"(zp), "f"(a * hv.x), "f"(a * hv.y), "f"(a * hv.z), "f"(a * hv.w)
                 : "memory");
}

// K5: out = z @ W^T + b   (block = (64,4); W transposed in smem, conflict-free)
__global__ void k_out(const float* __restrict__ Ww, const float* __restrict__ Wb,
                      float* __restrict__ out, int n) {
    __shared__ float Ws[DD * DD];   // Ws[k*64 + c] = Ww[c*64 + k]
    __shared__ float bs[DD];
    int tid = threadIdx.y * 64 + threadIdx.x;
    for (int i = tid; i < DD * DD; i += 256) {
        int c = i >> 6, k = i & 63;
        Ws[k * DD + c] = Ww[i];
    }
    if (tid < DD) bs[tid] = Wb[tid];
    __syncthreads();
    int row = blockIdx.x * 4 + threadIdx.y;
    if (row >= n) return;
    int c = threadIdx.x;
    const float* zr = g_z + (size_t)row * DD;
    float acc = bs[c];
#pragma unroll
    for (int k = 0; k < DD; k += 4) {
        float4 zv = *reinterpret_cast<const float4*>(zr + k);
        acc += zv.x * Ws[(k + 0) * DD + c];
        acc += zv.y * Ws[(k + 1) * DD + c];
        acc += zv.z * Ws[(k + 2) * DD + c];
        acc += zv.w * Ws[(k + 3) * DD + c];
    }
    out[(size_t)row * DD + c] = acc;
}

// ---------------------------------------------------------------------------
extern "C" void kernel_launch(void* const* d_in, const int* in_sizes, int n_in,
                              void* d_out, int out_size) {
    const float* h   = (const float*)d_in[0];
    const float* tax = (const float*)d_in[1];
    const int*   src = (const int*)d_in[2];
    const int*   dst = (const int*)d_in[3];
    const float* wh  = (const float*)d_in[4];
    const float* Ww  = (const float*)d_in[5];
    const float* Wb  = (const float*)d_in[6];
    float* out = (float*)d_out;

    int n = in_sizes[0] / DD;
    int e = in_sizes[2];

    k_node<<<(int)(((long long)n * 32 + 255) / 256), 256>>>(h, tax, wh, n);        // 1
    k_edge<<<(int)(((long long)e * 8 + 255) / 256), 256>>>(tax, src, dst, e);      // 2
    k_zeroz<<<(n * (DD / 4) + 255) / 256, 256>>>(n);                               // 3
    k_scat<<<(int)(((long long)e * 16 + 255) / 256), 256>>>(h, src, dst, e);       // 4 <- profiled
    k_out<<<(n + 3) / 4, dim3(64, 4)>>>(Ww, Wb, out, n);                           // 5
}

// round 14
// speedup vs baseline: 2.6111x; 2.1265x over previous
#include <cuda_runtime.h>
#include <math.h>

static constexpr int NN = 100000;   // nodes (capacity)
static constexpr int EE = 1600000;  // edges (capacity)
static constexpr int DD = 64;
static constexpr int ROWS_PB = 16;  // rows per block in k_out

// Scratch (static device globals; no allocation anywhere).
// Per-launch invariants: k_node zeroes z / sf / st at the start of every
// launch (BSS zero makes the first run correct); g_Mi max is idempotent.
__device__ __align__(16) float  g_z[(size_t)NN * DD];  // 25.6 MB z accumulator
__device__ float  g_as[NN], g_ad[NN];                  // per-node logit halves
__device__ float  g_norm[NN];                          // ||tax_n||
__device__ int    g_Mi;                                // max norm (float bits; pos -> int cmp ok)
__device__ float  g_sf[NN], g_st[NN];                  // softmax denominators
__device__ __align__(8) float2 g_e2[EE];               // (e_f, e_t), original edge order

// ---------------------------------------------------------------------------
// K1: zero z + denominators, per-node dots a_s = h.wh[0:64], a_d = h.wh[64:],
//     ||tax||, block-reduced global max norm (1 atomic per block, not per warp)
__global__ void k_node(const float* __restrict__ h, const float* __restrict__ tax,
                       const float* __restrict__ wh, int n) {
    __shared__ float smax[8];
    int gt = blockIdx.x * blockDim.x + threadIdx.x;
    int w = gt >> 5, lane = gt & 31;
    if (gt < n * (DD / 4))
        reinterpret_cast<float4*>(g_z)[gt] = make_float4(0.f, 0.f, 0.f, 0.f);
    if (gt < n) { g_sf[gt] = 0.f; g_st[gt] = 0.f; }
    float nr = 0.f;
    if (w < n) {
        float2 hv = *reinterpret_cast<const float2*>(h + (size_t)w * DD + lane * 2);
        float2 tv = *reinterpret_cast<const float2*>(tax + (size_t)w * DD + lane * 2);
        float2 wa = *reinterpret_cast<const float2*>(wh + lane * 2);
        float2 wb = *reinterpret_cast<const float2*>(wh + DD + lane * 2);
        float ps = hv.x * wa.x + hv.y * wa.y;
        float pd = hv.x * wb.x + hv.y * wb.y;
        float nq = tv.x * tv.x + tv.y * tv.y;
#pragma unroll
        for (int o = 16; o; o >>= 1) {
            ps += __shfl_xor_sync(0xffffffffu, ps, o);
            pd += __shfl_xor_sync(0xffffffffu, pd, o);
            nq += __shfl_xor_sync(0xffffffffu, nq, o);
        }
        if (lane == 0) {
            g_as[w] = ps;
            g_ad[w] = pd;
            nr = sqrtf(nq);
            g_norm[w] = nr;
        }
    }
    // block max of nr (nonzero only on contributing lane0s; norms positive)
    float wm = nr;
#pragma unroll
    for (int o = 16; o; o >>= 1) wm = fmaxf(wm, __shfl_xor_sync(0xffffffffu, wm, o));
    if (lane == 0) smax[threadIdx.x >> 5] = wm;
    __syncthreads();
    if (threadIdx.x == 0) {
        float m = smax[0];
#pragma unroll
        for (int i = 1; i < 8; i++) m = fmaxf(m, smax[i]);
        if (m > 0.f) atomicMax(&g_Mi, __float_as_int(m));   // idempotent across replays
    }
}

// K2: fused edge pass, all fp32. Per-dst shift S_d = ||tax_d||*M - 80
// (d-only -> cancels in softmax; Cauchy-Schwarz bounds p-S_d in [-~64, 80]).
__global__ void k_edge(const float* __restrict__ tax, const int* __restrict__ src,
                       const int* __restrict__ dst, int e) {
    int gt = blockIdx.x * blockDim.x + threadIdx.x;
    int w = gt >> 3, l = gt & 7;
    if (w >= e) return;
    int s = src[w], d = dst[w];
    const float4* ts = reinterpret_cast<const float4*>(tax + (size_t)s * DD);
    const float4* td = reinterpret_cast<const float4*>(tax + (size_t)d * DD);
    float4 a0 = ts[l * 2],     b0 = td[l * 2];
    float4 a1 = ts[l * 2 + 1], b1 = td[l * 2 + 1];
    float p = a0.x * b0.x + a0.y * b0.y + a0.z * b0.z + a0.w * b0.w
            + a1.x * b1.x + a1.y * b1.y + a1.z * b1.z + a1.w * b1.w;
#pragma unroll
    for (int o = 4; o; o >>= 1) p += __shfl_xor_sync(0xffffffffu, p, o);
    if (l == 0) {
        float x = g_as[s] + g_ad[d];
        float wf = x >= 0.f ? x : 0.01f * x;      // leaky_relu(0.01); |wf| small
        float M = __int_as_float(g_Mi);
        float shift = g_norm[d] * M - 80.f;
        float ef = __expf(wf);
        float et = __expf(p - shift);
        atomicAdd(&g_sf[d], ef);
        atomicAdd(&g_st[d], et);
        g_e2[w] = make_float2(ef, et);
    }
}

// K3: edge-parallel scatter. 16 threads/edge, zero serial chains:
// alpha from denominators + h row gather + red.global.add.v4.
__global__ void k_scat(const float* __restrict__ h, const int* __restrict__ src,
                       const int* __restrict__ dst, int e) {
    int gt = blockIdx.x * blockDim.x + threadIdx.x;
    int w = gt >> 4, l = gt & 15;
    if (w >= e) return;
    int s = src[w], d = dst[w];
    float2 ev = g_e2[w];
    float a = ev.x * (0.5f / g_sf[d]) + ev.y * (0.5f / g_st[d]);
    float4 hv = *reinterpret_cast<const float4*>(h + (size_t)s * DD + l * 4);
    float* zp = g_z + (size_t)d * DD + l * 4;
    asm volatile("red.global.add.v4.f32 [%0], {%1, %2, %3, %4};"
                 :: "l"(zp), "f"(a * hv.x), "f"(a * hv.y), "f"(a * hv.z), "f"(a * hv.w)
                 : "memory");
}

// K4 (PROFILED SLOT): out = z @ W^T + b.
// Padded smem transpose (Ws[k][c] at k*65+c -> bank (k+c)%32: conflict-free
// for both the transpose store and the broadcast-read compute loop).
// 16 rows per block to amortize the W load.
__global__ void k_out(const float* __restrict__ Ww, const float* __restrict__ Wb,
                      float* __restrict__ out, int n) {
    __shared__ float Ws[DD][DD + 1];
    __shared__ float bs[DD];
    int tid = threadIdx.y * 64 + threadIdx.x;
    for (int i = tid; i < DD * DD; i += 256) {
        int c = i >> 6, k = i & 63;          // consecutive i: same c, k varies
        Ws[k][c] = Ww[i];                    // stride-65 smem: conflict-free
    }
    if (tid < DD) bs[tid] = Wb[tid];
    __syncthreads();
    int c = threadIdx.x;
#pragma unroll
    for (int r = 0; r < ROWS_PB / 4; r++) {
        int row = blockIdx.x * ROWS_PB + r * 4 + threadIdx.y;
        if (row < n) {
            const float* zr = g_z + (size_t)row * DD;
            float acc = bs[c];
#pragma unroll
            for (int k = 0; k < DD; k += 4) {
                float4 zv = *reinterpret_cast<const float4*>(zr + k);   // warp-broadcast
                acc += zv.x * Ws[k + 0][c];
                acc += zv.y * Ws[k + 1][c];
                acc += zv.z * Ws[k + 2][c];
                acc += zv.w * Ws[k + 3][c];
            }
            out[(size_t)row * DD + c] = acc;
        }
    }
}

// ---------------------------------------------------------------------------
extern "C" void kernel_launch(void* const* d_in, const int* in_sizes, int n_in,
                              void* d_out, int out_size) {
    const float* h   = (const float*)d_in[0];
    const float* tax = (const float*)d_in[1];
    const int*   src = (const int*)d_in[2];
    const int*   dst = (const int*)d_in[3];
    const float* wh  = (const float*)d_in[4];
    const float* Ww  = (const float*)d_in[5];
    const float* Wb  = (const float*)d_in[6];
    float* out = (float*)d_out;

    int n = in_sizes[0] / DD;
    int e = in_sizes[2];

    k_node<<<(int)(((long long)n * 32 + 255) / 256), 256>>>(h, tax, wh, n);        // 1
    k_edge<<<(int)(((long long)e * 8 + 255) / 256), 256>>>(tax, src, dst, e);      // 2
    k_scat<<<(int)(((long long)e * 16 + 255) / 256), 256>>>(h, src, dst, e);       // 3
    k_out<<<(n + ROWS_PB - 1) / ROWS_PB, dim3(64, 4)>>>(Ww, Wb, out, n);           // 4 <- profiled
}